// round 1
// baseline (speedup 1.0000x reference)
#include <cuda_runtime.h>
#include <cuda_bf16.h>
#include <cstdint>

// Problem constants
#define B_   32
#define C_   96
#define HID_ 576
#define H_   28
#define W_   28
#define P_   784            // H*W
#define NP_  25088          // B*P

// ---------------- device scratch (static globals, no runtime alloc) ----------------
__device__ __align__(16) int8_t g_qxt[NP_ * C_];     // [pix][c]  quantized input, ch-contiguous (2.4MB)
__device__ __align__(16) int8_t g_q1 [NP_ * HID_];   // [pix][c]  after conv1+bn+relu6+quant (14.5MB)
__device__ __align__(16) int8_t g_q2 [NP_ * HID_];   // [pix][c]  after dw+bn+relu6+quant   (14.5MB)
__device__ __align__(16) int8_t g_qw1[HID_ * C_];    // [co][ci]
__device__ __align__(16) int8_t g_qw3[C_ * HID_];    // [co][ci]
__device__ __align__(16) int8_t g_qw2[HID_ * 12];    // [c][tap], padded to 12
__device__ __align__(16) float  g_A1[HID_], g_B1[HID_];
__device__ __align__(16) float  g_A2[HID_], g_B2[HID_];
__device__ __align__(16) float  g_A3[C_],   g_B3[C_];
__device__ float g_c[4];   // [0]=1/ax1 [1]=1/ax2 [2]=1/ax3

// ---------------- helpers ----------------
__device__ __forceinline__ int dp4(int4 a, int4 b, int acc) {
    acc = __dp4a(a.x, b.x, acc);
    acc = __dp4a(a.y, b.y, acc);
    acc = __dp4a(a.z, b.z, acc);
    acc = __dp4a(a.w, b.w, acc);
    return acc;
}

// bn(acc) -> relu6 -> quantize to [-8,7] (round half-even, like jnp.round)
__device__ __forceinline__ int bn_relu6_quant(int acc, float A, float Bv, float inv_ax) {
    float f = fmaf((float)acc, A, Bv);
    f = fminf(fmaxf(f, 0.0f), 6.0f);
    f = f * inv_ax;
    f = fminf(fmaxf(f, -8.0f), 7.0f);
    return (int)rintf(f);
}

// ---------------- kernel: setup (quantize weights, fold BN) ----------------
__global__ void k_setup(const float* w1, const float* w2, const float* w3,
                        const float* aw1, const float* ax1,
                        const float* g1, const float* b1, const float* m1, const float* v1,
                        const float* aw2, const float* ax2,
                        const float* g2, const float* b2, const float* m2, const float* v2,
                        const float* aw3, const float* ax3,
                        const float* g3, const float* b3, const float* m3, const float* v3)
{
    int tid = blockIdx.x * blockDim.x + threadIdx.x;
    int nt  = gridDim.x * blockDim.x;
    float a1 = aw1[0], a2 = aw2[0], a3 = aw3[0];

    for (int i = tid; i < HID_ * C_; i += nt)
        g_qw1[i] = (int8_t)(int)rintf(fminf(fmaxf(w1[i] / a1, -8.0f), 7.0f));
    for (int i = tid; i < C_ * HID_; i += nt)
        g_qw3[i] = (int8_t)(int)rintf(fminf(fmaxf(w3[i] / a3, -8.0f), 7.0f));
    for (int i = tid; i < HID_ * 9; i += nt) {
        int c = i / 9, tap = i % 9;
        g_qw2[c * 12 + tap] = (int8_t)(int)rintf(fminf(fmaxf(w2[i] / a2, -8.0f), 7.0f));
    }
    for (int c = tid; c < HID_; c += nt) {
        float s1 = g1[c] / sqrtf(v1[c] + 1e-5f);
        g_A1[c] = ax1[0] * a1 * s1;
        g_B1[c] = b1[c] - m1[c] * s1;
        float s2 = g2[c] / sqrtf(v2[c] + 1e-5f);
        g_A2[c] = ax2[0] * a2 * s2;
        g_B2[c] = b2[c] - m2[c] * s2;
    }
    for (int c = tid; c < C_; c += nt) {
        float s3 = g3[c] / sqrtf(v3[c] + 1e-5f);
        g_A3[c] = ax3[0] * a3 * s3;
        g_B3[c] = b3[c] - m3[c] * s3;
    }
    if (tid == 0) {
        g_c[0] = 1.0f / ax1[0];
        g_c[1] = 1.0f / ax2[0];
        g_c[2] = 1.0f / ax3[0];
    }
}

// ---------------- kernel: quantize + transpose x (NCHW fp32 -> [pix][c] int8) ----------------
// grid: B * 25 blocks (32-pixel tiles), 256 threads
__global__ void k_quantx(const float* __restrict__ x, const float* __restrict__ ax1)
{
    __shared__ int8_t sq[C_ * 36];   // [c][j], stride 36 to dodge conflicts
    int t  = threadIdx.x;
    int n  = blockIdx.x / 25;
    int p0 = (blockIdx.x % 25) * 32;
    float a = ax1[0];

#pragma unroll
    for (int r = 0; r < 12; r++) {
        int idx = t + r * 256;           // 3072 = 96c * 32j
        int c = idx >> 5, j = idx & 31;
        int p = p0 + j;
        float val = (p < P_) ? x[(n * C_ + c) * P_ + p] : 0.0f;
        float q = rintf(fminf(fmaxf(val / a, -8.0f), 7.0f));
        sq[c * 36 + j] = (int8_t)(int)q;
    }
    __syncthreads();
#pragma unroll
    for (int r = 0; r < 3; r++) {
        int idx = t + r * 256;           // 768 ints = 32 pixels * 24 ints
        int j = idx / 24, ii = idx % 24;
        int p = p0 + j;
        if (p < P_) {
            int b0 = (int)sq[(ii * 4 + 0) * 36 + j] & 255;
            int b1 = (int)sq[(ii * 4 + 1) * 36 + j] & 255;
            int b2 = (int)sq[(ii * 4 + 2) * 36 + j] & 255;
            int b3 = (int)sq[(ii * 4 + 3) * 36 + j] & 255;
            reinterpret_cast<int*>(g_qxt)[(n * P_ + p) * 24 + ii] =
                b0 | (b1 << 8) | (b2 << 16) | (b3 << 24);
        }
    }
}

// ---------------- kernel: conv1 1x1 (96 -> 576) + bn1 + relu6 + quant ----------------
// GEMM M=576, N=25088, K=96. Tile 64co x 64pix, 256 threads, thread = 4co x 4pix.
// grid: (392, 9)
__global__ __launch_bounds__(256) void k_conv1()
{
    __shared__ __align__(16) int sW[64 * 24];   // [co][k] 96B rows
    __shared__ __align__(16) int sX[64 * 28];   // [pix][k] padded stride 28 (conflict-free int4)
    int t    = threadIdx.x;
    int pix0 = blockIdx.x * 64;
    int co0  = blockIdx.y * 64;
    const int* gw = reinterpret_cast<const int*>(g_qw1);
    const int* gx = reinterpret_cast<const int*>(g_qxt);

#pragma unroll
    for (int r = 0; r < 6; r++) {
        int idx = t + r * 256;             // 1536 ints
        int row = idx / 24, k = idx % 24;
        sW[idx] = gw[(co0 + row) * 24 + k];
        sX[row * 28 + k] = gx[(pix0 + row) * 24 + k];
    }
    __syncthreads();

    int tx = t & 15, ty = t >> 4;
    int acc[4][4];
#pragma unroll
    for (int i = 0; i < 4; i++)
#pragma unroll
        for (int j = 0; j < 4; j++) acc[i][j] = 0;

#pragma unroll
    for (int g = 0; g < 6; g++) {
        int4 wv[4], xv[4];
#pragma unroll
        for (int i = 0; i < 4; i++)
            wv[i] = *reinterpret_cast<const int4*>(&sW[(ty * 4 + i) * 24 + g * 4]);
#pragma unroll
        for (int j = 0; j < 4; j++)
            xv[j] = *reinterpret_cast<const int4*>(&sX[(tx + 16 * j) * 28 + g * 4]);
#pragma unroll
        for (int i = 0; i < 4; i++)
#pragma unroll
            for (int j = 0; j < 4; j++)
                acc[i][j] = dp4(wv[i], xv[j], acc[i][j]);
    }

    float inv2 = g_c[1];
    int cbase = co0 + ty * 4;
    float Av[4], Bv[4];
#pragma unroll
    for (int i = 0; i < 4; i++) { Av[i] = g_A1[cbase + i]; Bv[i] = g_B1[cbase + i]; }

#pragma unroll
    for (int j = 0; j < 4; j++) {
        int pix = pix0 + tx + 16 * j;
        int q0 = bn_relu6_quant(acc[0][j], Av[0], Bv[0], inv2);
        int q1 = bn_relu6_quant(acc[1][j], Av[1], Bv[1], inv2);
        int q2 = bn_relu6_quant(acc[2][j], Av[2], Bv[2], inv2);
        int q3 = bn_relu6_quant(acc[3][j], Av[3], Bv[3], inv2);
        *reinterpret_cast<char4*>(&g_q1[pix * HID_ + cbase]) =
            make_char4((char)q0, (char)q1, (char)q2, (char)q3);
    }
}

// ---------------- kernel: depthwise 3x3 + bn2 + relu6 + quant ----------------
// grid: B*H blocks, 288 threads (144 ch-groups x 2 x-halves)
__global__ __launch_bounds__(288) void k_dw()
{
    int t  = threadIdx.x;
    int cg = t % 144;            // channel group of 4
    int xh = t / 144;            // 0/1
    int y  = blockIdx.x % H_;
    int n  = blockIdx.x / H_;
    const int* gq1 = reinterpret_cast<const int*>(g_q1);

    int c0 = cg * 4;
    int wv[9][4];
#pragma unroll
    for (int tap = 0; tap < 9; tap++)
#pragma unroll
        for (int k = 0; k < 4; k++)
            wv[tap][k] = (int)g_qw2[(c0 + k) * 12 + tap];

    float4 A = *reinterpret_cast<const float4*>(&g_A2[c0]);
    float4 Bv = *reinterpret_cast<const float4*>(&g_B2[c0]);
    float inv3 = g_c[2];
    int rowbase = n * P_ + y * W_;

    for (int xx = xh; xx < W_; xx += 2) {
        int a0 = 0, a1 = 0, a2 = 0, a3 = 0;
#pragma unroll
        for (int dy = -1; dy <= 1; dy++) {
            int yy = y + dy;
            if ((unsigned)yy >= H_) continue;
#pragma unroll
            for (int dx = -1; dx <= 1; dx++) {
                int xn = xx + dx;
                if ((unsigned)xn >= W_) continue;
                int v = gq1[((n * P_ + yy * W_ + xn) * 144) + cg];
                int tap = (dy + 1) * 3 + (dx + 1);
                a0 += ( v        & 255) * wv[tap][0];   // values 0..7, unsigned-safe
                a1 += ((v >> 8)  & 255) * wv[tap][1];
                a2 += ((v >> 16) & 255) * wv[tap][2];
                a3 += ((v >> 24) & 255) * wv[tap][3];
            }
        }
        int q0 = bn_relu6_quant(a0, A.x, Bv.x, inv3);
        int q1 = bn_relu6_quant(a1, A.y, Bv.y, inv3);
        int q2 = bn_relu6_quant(a2, A.z, Bv.z, inv3);
        int q3 = bn_relu6_quant(a3, A.w, Bv.w, inv3);
        reinterpret_cast<int*>(g_q2)[(rowbase + xx) * 144 + cg] =
            (q0 & 255) | ((q1 & 255) << 8) | ((q2 & 255) << 16) | ((q3 & 255) << 24);
    }
}

// ---------------- kernel: conv3 1x1 (576 -> 96) + bn3 + residual ----------------
// GEMM M=96, N=25088, K=576. Full W3 + X tile in dynamic smem.
// grid: 392 blocks, 256 threads, thread = 6co x 4pix.
#define SW3_INTS  (96 * 144)          // 13824
#define SX3_STRIDE 148                // conflict-free int4 (37 mod 8 coprime)
#define SX3_INTS  (64 * SX3_STRIDE)   // 9472
#define SMEM3_BYTES ((SW3_INTS + SX3_INTS) * 4)

__global__ __launch_bounds__(256) void k_conv3(const float* __restrict__ x,
                                               float* __restrict__ out)
{
    extern __shared__ __align__(16) int smem3[];
    int* sW = smem3;
    int* sX = smem3 + SW3_INTS;
    int t    = threadIdx.x;
    int pix0 = blockIdx.x * 64;
    const int* gw = reinterpret_cast<const int*>(g_qw3);
    const int* gx = reinterpret_cast<const int*>(g_q2);

#pragma unroll
    for (int r = 0; r < 54; r++) sW[t + r * 256] = gw[t + r * 256];
#pragma unroll
    for (int r = 0; r < 36; r++) {
        int idx = t + r * 256;            // 9216 = 64 rows * 144
        int row = idx / 144, k = idx % 144;
        sX[row * SX3_STRIDE + k] = gx[(pix0 + row) * 144 + k];
    }
    __syncthreads();

    int tx = t & 15, ty = t >> 4;
    int acc[6][4];
#pragma unroll
    for (int i = 0; i < 6; i++)
#pragma unroll
        for (int j = 0; j < 4; j++) acc[i][j] = 0;

    for (int g = 0; g < 36; g++) {
        int4 wv[6], xv[4];
#pragma unroll
        for (int i = 0; i < 6; i++)
            wv[i] = *reinterpret_cast<const int4*>(&sW[(ty * 6 + i) * 144 + g * 4]);
#pragma unroll
        for (int j = 0; j < 4; j++)
            xv[j] = *reinterpret_cast<const int4*>(&sX[(tx + 16 * j) * SX3_STRIDE + g * 4]);
#pragma unroll
        for (int i = 0; i < 6; i++)
#pragma unroll
            for (int j = 0; j < 4; j++)
                acc[i][j] = dp4(wv[i], xv[j], acc[i][j]);
    }

    int cbase = ty * 6;
    float Av[6], Bv[6];
#pragma unroll
    for (int i = 0; i < 6; i++) { Av[i] = g_A3[cbase + i]; Bv[i] = g_B3[cbase + i]; }

#pragma unroll
    for (int j = 0; j < 4; j++) {
        int pix = pix0 + tx + 16 * j;
        int n = pix / P_, p = pix % P_;
#pragma unroll
        for (int i = 0; i < 6; i++) {
            int off = (n * C_ + cbase + i) * P_ + p;
            out[off] = x[off] + fmaf((float)acc[i][j], Av[i], Bv[i]);
        }
    }
}

// ---------------- launch ----------------
extern "C" void kernel_launch(void* const* d_in, const int* in_sizes, int n_in,
                              void* d_out, int out_size)
{
    const float* x   = (const float*)d_in[0];
    const float* w1  = (const float*)d_in[1];
    const float* w2  = (const float*)d_in[2];
    const float* w3  = (const float*)d_in[3];
    const float* aw1 = (const float*)d_in[4];
    const float* ax1 = (const float*)d_in[5];
    const float* g1  = (const float*)d_in[6];
    const float* b1  = (const float*)d_in[7];
    const float* m1  = (const float*)d_in[8];
    const float* v1  = (const float*)d_in[9];
    const float* aw2 = (const float*)d_in[10];
    const float* ax2 = (const float*)d_in[11];
    const float* g2  = (const float*)d_in[12];
    const float* b2  = (const float*)d_in[13];
    const float* m2  = (const float*)d_in[14];
    const float* v2  = (const float*)d_in[15];
    const float* aw3 = (const float*)d_in[16];
    const float* ax3 = (const float*)d_in[17];
    const float* g3  = (const float*)d_in[18];
    const float* b3  = (const float*)d_in[19];
    const float* m3  = (const float*)d_in[20];
    const float* v3  = (const float*)d_in[21];
    float* out = (float*)d_out;

    k_setup<<<32, 256>>>(w1, w2, w3, aw1, ax1, g1, b1, m1, v1,
                         aw2, ax2, g2, b2, m2, v2, aw3, ax3, g3, b3, m3, v3);
    k_quantx<<<B_ * 25, 256>>>(x, ax1);
    k_conv1<<<dim3(NP_ / 64, HID_ / 64), 256>>>();
    k_dw<<<B_ * H_, 288>>>();
    cudaFuncSetAttribute(k_conv3, cudaFuncAttributeMaxDynamicSharedMemorySize, SMEM3_BYTES);
    k_conv3<<<NP_ / 64, 256, SMEM3_BYTES>>>(x, out);
}

// round 3
// speedup vs baseline: 1.1896x; 1.1896x over previous
#include <cuda_runtime.h>
#include <cuda_bf16.h>
#include <cstdint>

// Problem constants
#define B_   32
#define C_   96
#define HID_ 576
#define H_   28
#define W_   28
#define P_   784            // H*W
#define NP_  25088          // B*P

// ---------------- device scratch (static globals, no runtime alloc) ----------------
__device__ __align__(16) int8_t g_qxt[NP_ * C_];     // [pix][c]  quantized input, ch-contiguous
// channel-planar q1 with halo: [c][n][30 rows][32 bytes]; rows 1..28 = y 0..27, cols 0..27 = x
__device__ __align__(16) int8_t g_q1p[HID_ * B_ * 30 * 32];   // 17.7MB
__device__ __align__(16) int8_t g_q2 [NP_ * HID_];   // [pix][c]  after dw+bn+relu6+quant
__device__ __align__(16) int8_t g_qw1[HID_ * C_];    // [co][ci]
__device__ __align__(16) int8_t g_qw3[C_ * HID_];    // [co][ci]
__device__ __align__(16) int    g_qw2r[HID_ * 4];    // [c][row]: bytes (w0,w1,w2,0) per row
__device__ __align__(16) float  g_A1[HID_], g_B1[HID_];
__device__ __align__(16) float  g_A2[HID_], g_B2[HID_];
__device__ __align__(16) float  g_A3[C_],   g_B3[C_];
__device__ float g_c[4];   // [0]=1/ax2 [1]=min(6/ax2,7) [2]=1/ax3 [3]=min(6/ax3,7)

// ---------------- helpers ----------------
__device__ __forceinline__ int dp4(int4 a, int4 b, int acc) {
    acc = __dp4a(a.x, b.x, acc);
    acc = __dp4a(a.y, b.y, acc);
    acc = __dp4a(a.z, b.z, acc);
    acc = __dp4a(a.w, b.w, acc);
    return acc;
}

// signed dp4a with byte_perm-built window
__device__ __forceinline__ int dpw(int lo, int hi, int sel, int w, int acc) {
    return __dp4a((int)__byte_perm((unsigned)lo, (unsigned)hi, (unsigned)sel), w, acc);
}

// folded bn -> relu6 -> quantize: rint(min(max(acc*A+B, 0)*inv, cmax))
__device__ __forceinline__ int bnq(int acc, float A, float Bv, float inv, float cm) {
    float f = fmaf((float)acc, A, Bv);
    f = fmaxf(f, 0.0f) * inv;
    f = fminf(f, cm);
    return (int)rintf(f);
}

// ---------------- kernel: setup (quantize weights, fold BN) ----------------
__global__ void k_setup(const float* w1, const float* w2, const float* w3,
                        const float* aw1, const float* ax1,
                        const float* g1, const float* b1, const float* m1, const float* v1,
                        const float* aw2, const float* ax2,
                        const float* g2, const float* b2, const float* m2, const float* v2,
                        const float* aw3, const float* ax3,
                        const float* g3, const float* b3, const float* m3, const float* v3)
{
    int tid = blockIdx.x * blockDim.x + threadIdx.x;
    int nt  = gridDim.x * blockDim.x;
    float a1 = aw1[0], a2 = aw2[0], a3 = aw3[0];

    for (int i = tid; i < HID_ * C_; i += nt)
        g_qw1[i] = (int8_t)(int)rintf(fminf(fmaxf(w1[i] / a1, -8.0f), 7.0f));
    for (int i = tid; i < C_ * HID_; i += nt)
        g_qw3[i] = (int8_t)(int)rintf(fminf(fmaxf(w3[i] / a3, -8.0f), 7.0f));
    for (int c = tid; c < HID_; c += nt) {
        int q[9];
#pragma unroll
        for (int tp = 0; tp < 9; tp++)
            q[tp] = (int)rintf(fminf(fmaxf(w2[c * 9 + tp] / a2, -8.0f), 7.0f));
#pragma unroll
        for (int r = 0; r < 3; r++)
            g_qw2r[c * 4 + r] = (q[3*r] & 255) | ((q[3*r+1] & 255) << 8) | ((q[3*r+2] & 255) << 16);
        float s1 = g1[c] / sqrtf(v1[c] + 1e-5f);
        g_A1[c] = ax1[0] * a1 * s1;
        g_B1[c] = b1[c] - m1[c] * s1;
        float s2 = g2[c] / sqrtf(v2[c] + 1e-5f);
        g_A2[c] = ax2[0] * a2 * s2;
        g_B2[c] = b2[c] - m2[c] * s2;
    }
    for (int c = tid; c < C_; c += nt) {
        float s3 = g3[c] / sqrtf(v3[c] + 1e-5f);
        g_A3[c] = ax3[0] * a3 * s3;
        g_B3[c] = b3[c] - m3[c] * s3;
    }
    if (tid == 0) {
        g_c[0] = 1.0f / ax2[0];
        g_c[1] = fminf(6.0f / ax2[0], 7.0f);
        g_c[2] = 1.0f / ax3[0];
        g_c[3] = fminf(6.0f / ax3[0], 7.0f);
    }
}

// ---------------- kernel: zero q1p (halo padding comes for free) ----------------
__global__ void k_zero()
{
    int i = blockIdx.x * blockDim.x + threadIdx.x;
    int4* p = reinterpret_cast<int4*>(g_q1p);
    int4 z = make_int4(0, 0, 0, 0);
#pragma unroll
    for (int r = 0; r < 4; r++)
        p[i + r * 276480] = z;       // 1105920 int4 total
}

// ---------------- kernel: quantize + transpose x (NCHW fp32 -> [pix][c] int8) ----------------
__global__ void k_quantx(const float* __restrict__ x, const float* __restrict__ ax1)
{
    __shared__ int8_t sq[C_ * 36];
    int t  = threadIdx.x;
    int n  = blockIdx.x / 25;
    int p0 = (blockIdx.x % 25) * 32;
    float a = ax1[0];

#pragma unroll
    for (int r = 0; r < 12; r++) {
        int idx = t + r * 256;
        int c = idx >> 5, j = idx & 31;
        int p = p0 + j;
        float val = (p < P_) ? x[(n * C_ + c) * P_ + p] : 0.0f;
        float q = rintf(fminf(fmaxf(val / a, -8.0f), 7.0f));
        sq[c * 36 + j] = (int8_t)(int)q;
    }
    __syncthreads();
#pragma unroll
    for (int r = 0; r < 3; r++) {
        int idx = t + r * 256;
        int j = idx / 24, ii = idx % 24;
        int p = p0 + j;
        if (p < P_) {
            int b0 = (int)sq[(ii * 4 + 0) * 36 + j] & 255;
            int b1 = (int)sq[(ii * 4 + 1) * 36 + j] & 255;
            int b2 = (int)sq[(ii * 4 + 2) * 36 + j] & 255;
            int b3 = (int)sq[(ii * 4 + 3) * 36 + j] & 255;
            reinterpret_cast<int*>(g_qxt)[(n * P_ + p) * 24 + ii] =
                b0 | (b1 << 8) | (b2 << 16) | (b3 << 24);
        }
    }
}

// ---------------- kernel: conv1 1x1 (96 -> 576) + bn1 + relu6 + quant -> planar ----------------
__global__ __launch_bounds__(256) void k_conv1()
{
    __shared__ __align__(16) int sW[64 * 24];
    __shared__ __align__(16) int sX[64 * 28];
    int t    = threadIdx.x;
    int pix0 = blockIdx.x * 64;
    int co0  = blockIdx.y * 64;
    const int* gw = reinterpret_cast<const int*>(g_qw1);
    const int* gx = reinterpret_cast<const int*>(g_qxt);

#pragma unroll
    for (int r = 0; r < 6; r++) {
        int idx = t + r * 256;
        int row = idx / 24, k = idx % 24;
        sW[idx] = gw[(co0 + row) * 24 + k];
        sX[row * 28 + k] = gx[(pix0 + row) * 24 + k];
    }
    __syncthreads();

    int tx = t & 15, ty = t >> 4;
    int acc[4][4];
#pragma unroll
    for (int i = 0; i < 4; i++)
#pragma unroll
        for (int j = 0; j < 4; j++) acc[i][j] = 0;

#pragma unroll
    for (int g = 0; g < 6; g++) {
        int4 wv[4], xv[4];
#pragma unroll
        for (int i = 0; i < 4; i++)
            wv[i] = *reinterpret_cast<const int4*>(&sW[(ty * 4 + i) * 24 + g * 4]);
#pragma unroll
        for (int j = 0; j < 4; j++)
            xv[j] = *reinterpret_cast<const int4*>(&sX[(tx + 16 * j) * 28 + g * 4]);
#pragma unroll
        for (int i = 0; i < 4; i++)
#pragma unroll
            for (int j = 0; j < 4; j++)
                acc[i][j] = dp4(wv[i], xv[j], acc[i][j]);
    }

    float inv = g_c[0], cm = g_c[1];
    int cbase = co0 + ty * 4;
    float Av[4], Bv[4];
#pragma unroll
    for (int i = 0; i < 4; i++) { Av[i] = g_A1[cbase + i]; Bv[i] = g_B1[cbase + i]; }

#pragma unroll
    for (int j = 0; j < 4; j++) {
        int pix = pix0 + tx + 16 * j;
        int n = pix / P_;
        int p = pix - n * P_;
        int y = p / W_;
        int xx = p - y * W_;
        int base = n * 960 + (y + 1) * 32 + xx;   // within one channel plane
#pragma unroll
        for (int i = 0; i < 4; i++) {
            int q = bnq(acc[i][j], Av[i], Bv[i], inv, cm);
            g_q1p[(cbase + i) * 30720 + base] = (int8_t)q;
        }
    }
}

// ---------------- kernel: depthwise 3x3 + bn2 + relu6 + quant ----------------
// grid: 32n * 7 ystrips * 8 cgroups = 1792 blocks, 288 threads (72 ch x 4 y)
__global__ __launch_bounds__(288) void k_dw()
{
    __shared__ __align__(16) int s_in[72 * 52];   // per-ch 48 ints padded to 52
    __shared__ __align__(16) int s_out[2016];     // 112 pix x 18 ints (72 ch)
    int t  = threadIdx.x;
    int b  = blockIdx.x;
    int cg = b & 7;
    int s  = (b >> 3) % 7;
    int n  = b / 56;
    int c0 = cg * 72;

    const int4* g4 = reinterpret_cast<const int4*>(g_q1p);
    int4* s4 = reinterpret_cast<int4*>(s_in);
#pragma unroll
    for (int it = 0; it < 3; it++) {
        int idx = t + it * 288;                   // 864 int4
        int c = idx / 12, r4 = idx % 12;
        s4[c * 13 + r4] = g4[((c0 + c) * 32 + n) * 60 + s * 8 + r4];
    }
    __syncthreads();

    int c = t % 72, y = t / 72;
    int gc = c0 + c;
    int w0 = g_qw2r[gc * 4 + 0];
    int w1 = g_qw2r[gc * 4 + 1];
    int w2 = g_qw2r[gc * 4 + 2];
    float A = g_A2[gc], Bv = g_B2[gc];
    float inv = g_c[2], cm = g_c[3];

    const int4* sb = s4 + c * 13 + y * 2;         // rows y, y+1, y+2
    int4 t0 = sb[0], t1 = sb[1], t2 = sb[2], t3 = sb[3], t4 = sb[4], t5 = sb[5];
    int r0[8] = {t0.x, t0.y, t0.z, t0.w, t1.x, t1.y, t1.z, t1.w};
    int r1[8] = {t2.x, t2.y, t2.z, t2.w, t3.x, t3.y, t3.z, t3.w};
    int r2[8] = {t4.x, t4.y, t4.z, t4.w, t5.x, t5.y, t5.z, t5.w};

    int8_t* so = reinterpret_cast<int8_t*>(s_out);
#pragma unroll
    for (int j = 0; j < 7; j++) {
        int p0 = j ? r0[j - 1] : 0, m0 = r0[j], q0 = r0[j + 1];
        int p1 = j ? r1[j - 1] : 0, m1 = r1[j], q1 = r1[j + 1];
        int p2 = j ? r2[j - 1] : 0, m2 = r2[j], q2 = r2[j + 1];
        int a0 = 0, a1 = 0, a2 = 0, a3 = 0;
        a0 = dpw(p0, m0, 0x5543, w0, a0);
        a1 = dpw(p0, m0, 0x6654, w0, a1);
        a2 = dpw(p0, m0, 0x7765, w0, a2);
        a3 = dpw(m0, q0, 0x4432, w0, a3);
        a0 = dpw(p1, m1, 0x5543, w1, a0);
        a1 = dpw(p1, m1, 0x6654, w1, a1);
        a2 = dpw(p1, m1, 0x7765, w1, a2);
        a3 = dpw(m1, q1, 0x4432, w1, a3);
        a0 = dpw(p2, m2, 0x5543, w2, a0);
        a1 = dpw(p2, m2, 0x6654, w2, a1);
        a2 = dpw(p2, m2, 0x7765, w2, a2);
        a3 = dpw(m2, q2, 0x4432, w2, a3);

        int pixb = (y * 28 + j * 4) * 72 + c;
        so[pixb          ] = (int8_t)bnq(a0, A, Bv, inv, cm);
        so[pixb + 72     ] = (int8_t)bnq(a1, A, Bv, inv, cm);
        so[pixb + 144    ] = (int8_t)bnq(a2, A, Bv, inv, cm);
        so[pixb + 216    ] = (int8_t)bnq(a3, A, Bv, inv, cm);
    }
    __syncthreads();

    int pbase = n * P_ + s * 112;
    int* gq2 = reinterpret_cast<int*>(g_q2);
#pragma unroll
    for (int it = 0; it < 7; it++) {
        int idx = t + it * 288;                   // 2016 ints
        int pix = idx / 18, k = idx % 18;
        gq2[(pbase + pix) * 144 + cg * 18 + k] = s_out[idx];
    }
}

// ---------------- kernel: conv3 1x1 (576 -> 96) + bn3 + residual ----------------
#define SW3_INTS  (96 * 144)
#define SX3_STRIDE 148
#define SX3_INTS  (64 * SX3_STRIDE)
#define SMEM3_BYTES ((SW3_INTS + SX3_INTS) * 4)

__global__ __launch_bounds__(256) void k_conv3(const float* __restrict__ x,
                                               float* __restrict__ out)
{
    extern __shared__ __align__(16) int smem3[];
    int* sW = smem3;
    int* sX = smem3 + SW3_INTS;
    int t    = threadIdx.x;
    int pix0 = blockIdx.x * 64;
    const int* gw = reinterpret_cast<const int*>(g_qw3);
    const int* gx = reinterpret_cast<const int*>(g_q2);

#pragma unroll
    for (int r = 0; r < 54; r++) sW[t + r * 256] = gw[t + r * 256];
#pragma unroll
    for (int r = 0; r < 36; r++) {
        int idx = t + r * 256;
        int row = idx / 144, k = idx % 144;
        sX[row * SX3_STRIDE + k] = gx[(pix0 + row) * 144 + k];
    }
    __syncthreads();

    int tx = t & 15, ty = t >> 4;
    int acc[6][4];
#pragma unroll
    for (int i = 0; i < 6; i++)
#pragma unroll
        for (int j = 0; j < 4; j++) acc[i][j] = 0;

    for (int g = 0; g < 36; g++) {
        int4 wv[6], xv[4];
#pragma unroll
        for (int i = 0; i < 6; i++)
            wv[i] = *reinterpret_cast<const int4*>(&sW[(ty * 6 + i) * 144 + g * 4]);
#pragma unroll
        for (int j = 0; j < 4; j++)
            xv[j] = *reinterpret_cast<const int4*>(&sX[(tx + 16 * j) * SX3_STRIDE + g * 4]);
#pragma unroll
        for (int i = 0; i < 6; i++)
#pragma unroll
            for (int j = 0; j < 4; j++)
                acc[i][j] = dp4(wv[i], xv[j], acc[i][j]);
    }

    int cbase = ty * 6;
    float Av[6], Bv[6];
#pragma unroll
    for (int i = 0; i < 6; i++) { Av[i] = g_A3[cbase + i]; Bv[i] = g_B3[cbase + i]; }

#pragma unroll
    for (int j = 0; j < 4; j++) {
        int pix = pix0 + tx + 16 * j;
        int n = pix / P_, p = pix % P_;
#pragma unroll
        for (int i = 0; i < 6; i++) {
            int off = (n * C_ + cbase + i) * P_ + p;
            out[off] = x[off] + fmaf((float)acc[i][j], Av[i], Bv[i]);
        }
    }
}

// ---------------- launch ----------------
extern "C" void kernel_launch(void* const* d_in, const int* in_sizes, int n_in,
                              void* d_out, int out_size)
{
    const float* x   = (const float*)d_in[0];
    const float* w1  = (const float*)d_in[1];
    const float* w2  = (const float*)d_in[2];
    const float* w3  = (const float*)d_in[3];
    const float* aw1 = (const float*)d_in[4];
    const float* ax1 = (const float*)d_in[5];
    const float* g1  = (const float*)d_in[6];
    const float* b1  = (const float*)d_in[7];
    const float* m1  = (const float*)d_in[8];
    const float* v1  = (const float*)d_in[9];
    const float* aw2 = (const float*)d_in[10];
    const float* ax2 = (const float*)d_in[11];
    const float* g2  = (const float*)d_in[12];
    const float* b2  = (const float*)d_in[13];
    const float* m2  = (const float*)d_in[14];
    const float* v2  = (const float*)d_in[15];
    const float* aw3 = (const float*)d_in[16];
    const float* ax3 = (const float*)d_in[17];
    const float* g3  = (const float*)d_in[18];
    const float* b3  = (const float*)d_in[19];
    const float* m3  = (const float*)d_in[20];
    const float* v3  = (const float*)d_in[21];
    float* out = (float*)d_out;

    k_setup<<<32, 256>>>(w1, w2, w3, aw1, ax1, g1, b1, m1, v1,
                         aw2, ax2, g2, b2, m2, v2, aw3, ax3, g3, b3, m3, v3);
    k_zero<<<1080, 256>>>();
    k_quantx<<<B_ * 25, 256>>>(x, ax1);
    k_conv1<<<dim3(NP_ / 64, HID_ / 64), 256>>>();
    k_dw<<<1792, 288>>>();
    cudaFuncSetAttribute(k_conv3, cudaFuncAttributeMaxDynamicSharedMemorySize, SMEM3_BYTES);
    k_conv3<<<NP_ / 64, 256, SMEM3_BYTES>>>(x, out);
}

// round 5
// speedup vs baseline: 1.2277x; 1.0321x over previous
#include <cuda_runtime.h>
#include <cuda_bf16.h>
#include <cstdint>

// Problem constants
#define B_   32
#define C_   96
#define HID_ 576
#define H_   28
#define W_   28
#define P_   784
#define NP_  25088

// ---------------- device scratch ----------------
__device__ __align__(16) int8_t g_qxt[NP_ * C_];              // [pix][96] int8
__device__ __align__(16) int8_t g_q1p[HID_ * B_ * 30 * 32];   // planar halo layout
__device__ __align__(16) int8_t g_q2 [NP_ * HID_];            // [pix][576] int8
__device__ __align__(16) int8_t g_qw1[HID_ * C_];             // [co][96]
__device__ __align__(16) int8_t g_qw3[C_ * HID_];             // [co][576]
__device__ __align__(16) int    g_qw2r[HID_ * 4];
__device__ __align__(16) float  g_A1[HID_], g_B1[HID_];
__device__ __align__(16) float  g_A2[HID_], g_B2[HID_];
__device__ __align__(16) float  g_A3[C_],   g_B3[C_];
__device__ float g_c[4];   // [0]=1/ax2 [1]=min(6/ax2,7) [2]=1/ax3 [3]=min(6/ax3,7)

// ---------------- helpers ----------------
__device__ __forceinline__ void mma8(int* c, int a0, int a1, int a2, int a3,
                                     int b0, int b1) {
    asm volatile("mma.sync.aligned.m16n8k32.row.col.s32.s8.s8.s32 "
        "{%0,%1,%2,%3}, {%4,%5,%6,%7}, {%8,%9}, {%0,%1,%2,%3};"
        : "+r"(c[0]), "+r"(c[1]), "+r"(c[2]), "+r"(c[3])
        : "r"(a0), "r"(a1), "r"(a2), "r"(a3), "r"(b0), "r"(b1));
}
__device__ __forceinline__ int dpw(int lo, int hi, int sel, int w, int acc) {
    return __dp4a((int)__byte_perm((unsigned)lo, (unsigned)hi, (unsigned)sel), w, acc);
}
__device__ __forceinline__ int bnq(int acc, float A, float Bv, float inv, float cm) {
    float f = fmaf((float)acc, A, Bv);
    f = fmaxf(f, 0.0f) * inv;
    f = fminf(f, cm);
    return (int)rintf(f);
}

// ---------------- kernel: setup ----------------
__global__ void k_setup(const float* w1, const float* w2, const float* w3,
                        const float* aw1, const float* ax1,
                        const float* g1, const float* b1, const float* m1, const float* v1,
                        const float* aw2, const float* ax2,
                        const float* g2, const float* b2, const float* m2, const float* v2,
                        const float* aw3, const float* ax3,
                        const float* g3, const float* b3, const float* m3, const float* v3)
{
    int tid = blockIdx.x * blockDim.x + threadIdx.x;
    int nt  = gridDim.x * blockDim.x;
    float a1 = aw1[0], a2 = aw2[0], a3 = aw3[0];

    for (int i = tid; i < HID_ * C_; i += nt)
        g_qw1[i] = (int8_t)(int)rintf(fminf(fmaxf(w1[i] / a1, -8.0f), 7.0f));
    for (int i = tid; i < C_ * HID_; i += nt)
        g_qw3[i] = (int8_t)(int)rintf(fminf(fmaxf(w3[i] / a3, -8.0f), 7.0f));
    for (int c = tid; c < HID_; c += nt) {
        int q[9];
#pragma unroll
        for (int tp = 0; tp < 9; tp++)
            q[tp] = (int)rintf(fminf(fmaxf(w2[c * 9 + tp] / a2, -8.0f), 7.0f));
#pragma unroll
        for (int r = 0; r < 3; r++)
            g_qw2r[c * 4 + r] = (q[3*r] & 255) | ((q[3*r+1] & 255) << 8) | ((q[3*r+2] & 255) << 16);
        float s1 = g1[c] / sqrtf(v1[c] + 1e-5f);
        g_A1[c] = ax1[0] * a1 * s1;
        g_B1[c] = b1[c] - m1[c] * s1;
        float s2 = g2[c] / sqrtf(v2[c] + 1e-5f);
        g_A2[c] = ax2[0] * a2 * s2;
        g_B2[c] = b2[c] - m2[c] * s2;
    }
    for (int c = tid; c < C_; c += nt) {
        float s3 = g3[c] / sqrtf(v3[c] + 1e-5f);
        g_A3[c] = ax3[0] * a3 * s3;
        g_B3[c] = b3[c] - m3[c] * s3;
    }
    if (tid == 0) {
        g_c[0] = 1.0f / ax2[0];
        g_c[1] = fminf(6.0f / ax2[0], 7.0f);
        g_c[2] = 1.0f / ax3[0];
        g_c[3] = fminf(6.0f / ax3[0], 7.0f);
    }
}

// ---------------- kernel: halo-only zero of g_q1p ----------------
__global__ void k_zero()
{
    int pid = blockIdx.x * 256 + threadIdx.x;
    if (pid >= HID_ * B_) return;
    int4* p4 = reinterpret_cast<int4*>(g_q1p + (size_t)pid * 960);
    int4 z = make_int4(0, 0, 0, 0);
    p4[0] = z; p4[1] = z;
    p4[58] = z; p4[59] = z;
    int* pi = reinterpret_cast<int*>(g_q1p + (size_t)pid * 960);
#pragma unroll
    for (int r = 1; r < 29; r++) pi[r * 8 + 7] = 0;
}

// ---------------- kernel: quantize + transpose x ----------------
__global__ void k_quantx(const float* __restrict__ x, const float* __restrict__ ax1)
{
    __shared__ int8_t sq[C_ * 36];
    int t  = threadIdx.x;
    int n  = blockIdx.x / 25;
    int p0 = (blockIdx.x % 25) * 32;
    float a = ax1[0];

#pragma unroll
    for (int r = 0; r < 12; r++) {
        int idx = t + r * 256;
        int c = idx >> 5, j = idx & 31;
        int p = p0 + j;
        float val = (p < P_) ? x[(n * C_ + c) * P_ + p] : 0.0f;
        float q = rintf(fminf(fmaxf(val / a, -8.0f), 7.0f));
        sq[c * 36 + j] = (int8_t)(int)q;
    }
    __syncthreads();
#pragma unroll
    for (int r = 0; r < 3; r++) {
        int idx = t + r * 256;
        int j = idx / 24, ii = idx % 24;
        int p = p0 + j;
        if (p < P_) {
            int b0 = (int)sq[(ii * 4 + 0) * 36 + j] & 255;
            int b1 = (int)sq[(ii * 4 + 1) * 36 + j] & 255;
            int b2 = (int)sq[(ii * 4 + 2) * 36 + j] & 255;
            int b3 = (int)sq[(ii * 4 + 3) * 36 + j] & 255;
            reinterpret_cast<int*>(g_qxt)[(n * P_ + p) * 24 + ii] =
                b0 | (b1 << 8) | (b2 << 16) | (b3 << 24);
        }
    }
}

// ---------------- kernel: conv1 via mma.sync (112 pix x 144 co, K=96) ----------------
// 7 warps, each m16 x n144 (18 n-blocks), 3 k32 steps.
__global__ __launch_bounds__(224) void k_conv1m()
{
    __shared__ __align__(16) int sA[112 * 28];      // [pix][k] stride 28 words (conflict-free)
    __shared__ __align__(16) int sW[144 * 28];      // [co][k]  stride 28 words
    __shared__ __align__(16) int8_t sS[144 * 116];  // stage [co][pix] bytes
    __shared__ float sAf[144], sBf[144];

    int t = threadIdx.x, w = t >> 5, lane = t & 31;
    int q = lane >> 2, rr = lane & 3;
    int pix0 = blockIdx.x * 112;
    int co0  = blockIdx.y * 144;

    // load A: 112 rows x 96B (globally contiguous)
    {
        const int4* gA = reinterpret_cast<const int4*>(g_qxt + (size_t)pix0 * 96);
#pragma unroll
        for (int it = 0; it < 3; it++) {
            int i = t + it * 224;
            int r = i / 6, c = i % 6;
            *reinterpret_cast<int4*>(&sA[r * 28 + c * 4]) = gA[i];
        }
    }
    // load W: 144 rows x 96B
    {
        const int4* gW = reinterpret_cast<const int4*>(g_qw1 + (size_t)co0 * 96);
#pragma unroll
        for (int it = 0; it < 4; it++) {
            int i = t + it * 224;
            if (i < 864) {
                int r = i / 6, c = i % 6;
                *reinterpret_cast<int4*>(&sW[r * 28 + c * 4]) = gW[i];
            }
        }
    }
    for (int i = t; i < 144; i += 224) { sAf[i] = g_A1[co0 + i]; sBf[i] = g_B1[co0 + i]; }
    __syncthreads();

    int acc[18][4];
#pragma unroll
    for (int nb = 0; nb < 18; nb++)
#pragma unroll
        for (int j = 0; j < 4; j++) acc[nb][j] = 0;

    const int* ap = &sA[(w * 16 + q) * 28 + rr];
#pragma unroll
    for (int k = 0; k < 3; k++) {
        int a0 = ap[k * 8];
        int a1 = ap[k * 8 + 8 * 28];
        int a2 = ap[k * 8 + 4];
        int a3 = ap[k * 8 + 8 * 28 + 4];
#pragma unroll
        for (int nb = 0; nb < 18; nb++) {
            const int* bp = &sW[(nb * 8 + q) * 28 + rr + k * 8];
            mma8(acc[nb], a0, a1, a2, a3, bp[0], bp[4]);
        }
    }

    // epilogue: quantize into stage [co][pix]
    float inv = g_c[0], cm = g_c[1];
    int pr0 = w * 16 + q, pr1 = pr0 + 8;
#pragma unroll
    for (int nb = 0; nb < 18; nb++) {
        int ca = nb * 8 + rr * 2, cb = ca + 1;
        sS[ca * 116 + pr0] = (int8_t)bnq(acc[nb][0], sAf[ca], sBf[ca], inv, cm);
        sS[cb * 116 + pr0] = (int8_t)bnq(acc[nb][1], sAf[cb], sBf[cb], inv, cm);
        sS[ca * 116 + pr1] = (int8_t)bnq(acc[nb][2], sAf[ca], sBf[ca], inv, cm);
        sS[cb * 116 + pr1] = (int8_t)bnq(acc[nb][3], sAf[cb], sBf[cb], inv, cm);
    }
    __syncthreads();

    // coalesced copy to planar: 144 co x 4 rows x 7 ints
    int n = pix0 / P_;
    int yy = (pix0 % P_) / W_;
#pragma unroll
    for (int it = 0; it < 18; it++) {
        int i = t + it * 224;                 // 4032 total
        int co = i / 28, rem = i % 28, seg = rem / 7, wd = rem % 7;
        int val = *reinterpret_cast<const int*>(&sS[co * 116 + seg * 28 + wd * 4]);
        *reinterpret_cast<int*>(
            &g_q1p[(size_t)(co0 + co) * 30720 + n * 960 + (yy + seg + 1) * 32 + wd * 4]) = val;
    }
}

// ---------------- kernel: depthwise 3x3 + bn2 + relu6 + quant ----------------
__global__ __launch_bounds__(288) void k_dw()
{
    __shared__ __align__(16) int s_in[72 * 52];
    __shared__ __align__(16) int s_out[2016];
    int t  = threadIdx.x;
    int b  = blockIdx.x;
    int cg = b & 7;
    int s  = (b >> 3) % 7;
    int n  = b / 56;
    int c0 = cg * 72;

    const int4* g4 = reinterpret_cast<const int4*>(g_q1p);
    int4* s4 = reinterpret_cast<int4*>(s_in);
#pragma unroll
    for (int it = 0; it < 3; it++) {
        int idx = t + it * 288;
        int c = idx / 12, r4 = idx % 12;
        s4[c * 13 + r4] = g4[((c0 + c) * 32 + n) * 60 + s * 8 + r4];
    }
    __syncthreads();

    int c = t % 72, y = t / 72;
    int gc = c0 + c;
    int w0 = g_qw2r[gc * 4 + 0];
    int w1 = g_qw2r[gc * 4 + 1];
    int w2 = g_qw2r[gc * 4 + 2];
    float A = g_A2[gc], Bv = g_B2[gc];
    float inv = g_c[2], cm = g_c[3];

    const int4* sb = s4 + c * 13 + y * 2;
    int4 t0 = sb[0], t1 = sb[1], t2 = sb[2], t3 = sb[3], t4 = sb[4], t5 = sb[5];
    int r0[8] = {t0.x, t0.y, t0.z, t0.w, t1.x, t1.y, t1.z, t1.w};
    int r1[8] = {t2.x, t2.y, t2.z, t2.w, t3.x, t3.y, t3.z, t3.w};
    int r2[8] = {t4.x, t4.y, t4.z, t4.w, t5.x, t5.y, t5.z, t5.w};

    int8_t* so = reinterpret_cast<int8_t*>(s_out);
#pragma unroll
    for (int j = 0; j < 7; j++) {
        int p0 = j ? r0[j - 1] : 0, m0 = r0[j], q0 = r0[j + 1];
        int p1 = j ? r1[j - 1] : 0, m1 = r1[j], q1 = r1[j + 1];
        int p2 = j ? r2[j - 1] : 0, m2 = r2[j], q2 = r2[j + 1];
        int a0 = 0, a1 = 0, a2 = 0, a3 = 0;
        a0 = dpw(p0, m0, 0x5543, w0, a0);
        a1 = dpw(p0, m0, 0x6654, w0, a1);
        a2 = dpw(p0, m0, 0x7765, w0, a2);
        a3 = dpw(m0, q0, 0x4432, w0, a3);
        a0 = dpw(p1, m1, 0x5543, w1, a0);
        a1 = dpw(p1, m1, 0x6654, w1, a1);
        a2 = dpw(p1, m1, 0x7765, w1, a2);
        a3 = dpw(m1, q1, 0x4432, w1, a3);
        a0 = dpw(p2, m2, 0x5543, w2, a0);
        a1 = dpw(p2, m2, 0x6654, w2, a1);
        a2 = dpw(p2, m2, 0x7765, w2, a2);
        a3 = dpw(m2, q2, 0x4432, w2, a3);

        int pixb = (y * 28 + j * 4) * 72 + c;
        so[pixb      ] = (int8_t)bnq(a0, A, Bv, inv, cm);
        so[pixb + 72 ] = (int8_t)bnq(a1, A, Bv, inv, cm);
        so[pixb + 144] = (int8_t)bnq(a2, A, Bv, inv, cm);
        so[pixb + 216] = (int8_t)bnq(a3, A, Bv, inv, cm);
    }
    __syncthreads();

    int pbase = n * P_ + s * 112;
    int* gq2 = reinterpret_cast<int*>(g_q2);
#pragma unroll
    for (int it = 0; it < 7; it++) {
        int idx = t + it * 288;
        int pix = idx / 18, k = idx % 18;
        gq2[(pbase + pix) * 144 + cg * 18 + k] = s_out[idx];
    }
}

// ---------------- kernel: conv3 via mma.sync (112 pix x 48 co, K=576 in 3 chunks) ----------------
// 7 warps, each m16 x n48 (6 n-blocks), 6 k32 steps per chunk.
// smem union: [ sA 112x52 ints | sW 48x52 ints ]  vs  stage fp32 48x113
__global__ __launch_bounds__(224) void k_conv3m(const float* __restrict__ x,
                                                float* __restrict__ out)
{
    __shared__ __align__(16) int sU[112 * 52 + 48 * 52];    // 8320 ints = 33.3KB
    __shared__ float sAf[48], sBf[48];

    int* sA = sU;
    int* sW = sU + 112 * 52;
    float* stg = reinterpret_cast<float*>(sU);              // reused after compute

    int t = threadIdx.x, w = t >> 5, lane = t & 31;
    int q = lane >> 2, rr = lane & 3;
    int pix0 = blockIdx.x * 112;
    int co0  = blockIdx.y * 48;

    for (int i = t; i < 48; i += 224) { sAf[i] = g_A3[co0 + i]; sBf[i] = g_B3[co0 + i]; }

    int acc[6][4];
#pragma unroll
    for (int nb = 0; nb < 6; nb++)
#pragma unroll
        for (int j = 0; j < 4; j++) acc[nb][j] = 0;

    for (int ch = 0; ch < 3; ch++) {
        // A chunk: 112 rows x 192B
        {
#pragma unroll
            for (int it = 0; it < 6; it++) {
                int i = t + it * 224;                     // 1344 int4
                int r = i / 12, c = i % 12;
                *reinterpret_cast<int4*>(&sA[r * 52 + c * 4]) =
                    *reinterpret_cast<const int4*>(g_q2 + (size_t)(pix0 + r) * HID_ + ch * 192 + c * 16);
            }
        }
        // W chunk: 48 rows x 192B
        {
#pragma unroll
            for (int it = 0; it < 3; it++) {
                int i = t + it * 224;                     // 576 int4
                if (i < 576) {
                    int r = i / 12, c = i % 12;
                    *reinterpret_cast<int4*>(&sW[r * 52 + c * 4]) =
                        *reinterpret_cast<const int4*>(g_qw3 + (size_t)(co0 + r) * HID_ + ch * 192 + c * 16);
                }
            }
        }
        __syncthreads();

        const int* ap = &sA[(w * 16 + q) * 52 + rr];
#pragma unroll
        for (int k = 0; k < 6; k++) {
            int a0 = ap[k * 8];
            int a1 = ap[k * 8 + 8 * 52];
            int a2 = ap[k * 8 + 4];
            int a3 = ap[k * 8 + 8 * 52 + 4];
#pragma unroll
            for (int nb = 0; nb < 6; nb++) {
                const int* bp = &sW[(nb * 8 + q) * 52 + rr + k * 8];
                mma8(acc[nb], a0, a1, a2, a3, bp[0], bp[4]);
            }
        }
        __syncthreads();
    }

    // stage fp32 [co][pix], stride 113
    int pr0 = w * 16 + q, pr1 = pr0 + 8;
#pragma unroll
    for (int nb = 0; nb < 6; nb++) {
        int ca = nb * 8 + rr * 2, cb = ca + 1;
        stg[ca * 113 + pr0] = (float)acc[nb][0];
        stg[cb * 113 + pr0] = (float)acc[nb][1];
        stg[ca * 113 + pr1] = (float)acc[nb][2];
        stg[cb * 113 + pr1] = (float)acc[nb][3];
    }
    __syncthreads();

    // coalesced epilogue: out = x + fma(acc, A3, B3)
    int n = pix0 / P_;
    int prow = pix0 % P_;
#pragma unroll
    for (int it = 0; it < 24; it++) {
        int i = t + it * 224;                    // 5376 total
        int co = i / 112, p = i % 112;
        int off = (n * C_ + co0 + co) * P_ + prow + p;
        out[off] = x[off] + fmaf(stg[co * 113 + p], sAf[co], sBf[co]);
    }
}

// ---------------- launch ----------------
extern "C" void kernel_launch(void* const* d_in, const int* in_sizes, int n_in,
                              void* d_out, int out_size)
{
    const float* x   = (const float*)d_in[0];
    const float* w1  = (const float*)d_in[1];
    const float* w2  = (const float*)d_in[2];
    const float* w3  = (const float*)d_in[3];
    const float* aw1 = (const float*)d_in[4];
    const float* ax1 = (const float*)d_in[5];
    const float* g1  = (const float*)d_in[6];
    const float* b1  = (const float*)d_in[7];
    const float* m1  = (const float*)d_in[8];
    const float* v1  = (const float*)d_in[9];
    const float* aw2 = (const float*)d_in[10];
    const float* ax2 = (const float*)d_in[11];
    const float* g2  = (const float*)d_in[12];
    const float* b2  = (const float*)d_in[13];
    const float* m2  = (const float*)d_in[14];
    const float* v2  = (const float*)d_in[15];
    const float* aw3 = (const float*)d_in[16];
    const float* ax3 = (const float*)d_in[17];
    const float* g3  = (const float*)d_in[18];
    const float* b3  = (const float*)d_in[19];
    const float* m3  = (const float*)d_in[20];
    const float* v3  = (const float*)d_in[21];
    float* out = (float*)d_out;

    k_setup<<<32, 256>>>(w1, w2, w3, aw1, ax1, g1, b1, m1, v1,
                         aw2, ax2, g2, b2, m2, v2, aw3, ax3, g3, b3, m3, v3);
    k_zero<<<72, 256>>>();
    k_quantx<<<B_ * 25, 256>>>(x, ax1);
    k_conv1m<<<dim3(NP_ / 112, 4), 224>>>();
    k_dw<<<1792, 288>>>();
    k_conv3m<<<dim3(NP_ / 112, 2), 224>>>(x, out);
}

// round 6
// speedup vs baseline: 1.2367x; 1.0073x over previous
#include <cuda_runtime.h>
#include <cuda_bf16.h>
#include <cstdint>

// Problem constants
#define B_   32
#define C_   96
#define HID_ 576
#define H_   28
#define W_   28
#define P_   784
#define NP_  25088

// ---------------- device scratch ----------------
__device__ __align__(16) int8_t g_qxt[NP_ * C_];              // [pix][96] int8
__device__ __align__(16) int8_t g_q1p[HID_ * B_ * 30 * 32];   // planar halo layout
__device__ __align__(16) int8_t g_q2 [NP_ * HID_];            // [pix][576] int8
__device__ __align__(16) int8_t g_qw1[HID_ * C_];             // [co][96]
__device__ __align__(16) int8_t g_qw3[C_ * HID_];             // [co][576]
__device__ __align__(16) int    g_qw2r[HID_ * 4];
__device__ __align__(16) float  g_A1[HID_], g_B1[HID_];
__device__ __align__(16) float  g_A2[HID_], g_B2[HID_];
__device__ __align__(16) float  g_A3[C_],   g_B3[C_];
__device__ float g_c[4];   // [0]=1/ax2 [1]=min(6/ax2,7) [2]=1/ax3 [3]=min(6/ax3,7)

// ---------------- helpers ----------------
__device__ __forceinline__ void mma8(int* c, int a0, int a1, int a2, int a3,
                                     int b0, int b1) {
    asm volatile("mma.sync.aligned.m16n8k32.row.col.s32.s8.s8.s32 "
        "{%0,%1,%2,%3}, {%4,%5,%6,%7}, {%8,%9}, {%0,%1,%2,%3};"
        : "+r"(c[0]), "+r"(c[1]), "+r"(c[2]), "+r"(c[3])
        : "r"(a0), "r"(a1), "r"(a2), "r"(a3), "r"(b0), "r"(b1));
}
__device__ __forceinline__ uint32_t smem_u32(const void* p) {
    uint32_t a;
    asm("{ .reg .u64 t; cvta.to.shared.u64 t, %1; cvt.u32.u64 %0, t; }" : "=r"(a) : "l"(p));
    return a;
}
__device__ __forceinline__ void cpa16(uint32_t s, const void* g) {
    asm volatile("cp.async.cg.shared.global [%0], [%1], 16;" :: "r"(s), "l"(g));
}
#define CPCOMMIT() asm volatile("cp.async.commit_group;" ::: "memory")
#define CPWAIT0()  asm volatile("cp.async.wait_group 0;" ::: "memory")

__device__ __forceinline__ int dpw(int lo, int hi, int sel, int w, int acc) {
    return __dp4a((int)__byte_perm((unsigned)lo, (unsigned)hi, (unsigned)sel), w, acc);
}
__device__ __forceinline__ int bnq(int acc, float A, float Bv, float inv, float cm) {
    float f = fmaf((float)acc, A, Bv);
    f = fmaxf(f, 0.0f) * inv;
    f = fminf(f, cm);
    return (int)rintf(f);
}

// ---------------- kernel: setup ----------------
__global__ void k_setup(const float* w1, const float* w2, const float* w3,
                        const float* aw1, const float* ax1,
                        const float* g1, const float* b1, const float* m1, const float* v1,
                        const float* aw2, const float* ax2,
                        const float* g2, const float* b2, const float* m2, const float* v2,
                        const float* aw3, const float* ax3,
                        const float* g3, const float* b3, const float* m3, const float* v3)
{
    int tid = blockIdx.x * blockDim.x + threadIdx.x;
    int nt  = gridDim.x * blockDim.x;
    float a1 = aw1[0], a2 = aw2[0], a3 = aw3[0];

    for (int i = tid; i < HID_ * C_; i += nt)
        g_qw1[i] = (int8_t)(int)rintf(fminf(fmaxf(w1[i] / a1, -8.0f), 7.0f));
    for (int i = tid; i < C_ * HID_; i += nt)
        g_qw3[i] = (int8_t)(int)rintf(fminf(fmaxf(w3[i] / a3, -8.0f), 7.0f));
    for (int c = tid; c < HID_; c += nt) {
        int q[9];
#pragma unroll
        for (int tp = 0; tp < 9; tp++)
            q[tp] = (int)rintf(fminf(fmaxf(w2[c * 9 + tp] / a2, -8.0f), 7.0f));
#pragma unroll
        for (int r = 0; r < 3; r++)
            g_qw2r[c * 4 + r] = (q[3*r] & 255) | ((q[3*r+1] & 255) << 8) | ((q[3*r+2] & 255) << 16);
        float s1 = g1[c] / sqrtf(v1[c] + 1e-5f);
        g_A1[c] = ax1[0] * a1 * s1;
        g_B1[c] = b1[c] - m1[c] * s1;
        float s2 = g2[c] / sqrtf(v2[c] + 1e-5f);
        g_A2[c] = ax2[0] * a2 * s2;
        g_B2[c] = b2[c] - m2[c] * s2;
    }
    for (int c = tid; c < C_; c += nt) {
        float s3 = g3[c] / sqrtf(v3[c] + 1e-5f);
        g_A3[c] = ax3[0] * a3 * s3;
        g_B3[c] = b3[c] - m3[c] * s3;
    }
    if (tid == 0) {
        g_c[0] = 1.0f / ax2[0];
        g_c[1] = fminf(6.0f / ax2[0], 7.0f);
        g_c[2] = 1.0f / ax3[0];
        g_c[3] = fminf(6.0f / ax3[0], 7.0f);
    }
}

// ---------------- kernel: halo-only zero of g_q1p ----------------
__global__ void k_zero()
{
    int pid = blockIdx.x * 256 + threadIdx.x;
    if (pid >= HID_ * B_) return;
    int4* p4 = reinterpret_cast<int4*>(g_q1p + (size_t)pid * 960);
    int4 z = make_int4(0, 0, 0, 0);
    p4[0] = z; p4[1] = z;
    p4[58] = z; p4[59] = z;
    int* pi = reinterpret_cast<int*>(g_q1p + (size_t)pid * 960);
#pragma unroll
    for (int r = 1; r < 29; r++) pi[r * 8 + 7] = 0;
}

// ---------------- kernel: quantize + transpose x ----------------
__global__ void k_quantx(const float* __restrict__ x, const float* __restrict__ ax1)
{
    __shared__ int8_t sq[C_ * 36];
    int t  = threadIdx.x;
    int n  = blockIdx.x / 25;
    int p0 = (blockIdx.x % 25) * 32;
    float a = ax1[0];

#pragma unroll
    for (int r = 0; r < 12; r++) {
        int idx = t + r * 256;
        int c = idx >> 5, j = idx & 31;
        int p = p0 + j;
        float val = (p < P_) ? x[(n * C_ + c) * P_ + p] : 0.0f;
        float q = rintf(fminf(fmaxf(val / a, -8.0f), 7.0f));
        sq[c * 36 + j] = (int8_t)(int)q;
    }
    __syncthreads();
#pragma unroll
    for (int r = 0; r < 3; r++) {
        int idx = t + r * 256;
        int j = idx / 24, ii = idx % 24;
        int p = p0 + j;
        if (p < P_) {
            int b0 = (int)sq[(ii * 4 + 0) * 36 + j] & 255;
            int b1 = (int)sq[(ii * 4 + 1) * 36 + j] & 255;
            int b2 = (int)sq[(ii * 4 + 2) * 36 + j] & 255;
            int b3 = (int)sq[(ii * 4 + 3) * 36 + j] & 255;
            reinterpret_cast<int*>(g_qxt)[(n * P_ + p) * 24 + ii] =
                b0 | (b1 << 8) | (b2 << 16) | (b3 << 24);
        }
    }
}

// ---------------- kernel: conv1 via mma.sync (112 pix x 144 co, K=96) ----------------
// 448 threads / 14 warps: warp (r = w>>1 -> pixel rows, h = w&1 -> 72-co half), 9 n-blocks.
__global__ __launch_bounds__(448, 2) void k_conv1m()
{
    __shared__ __align__(16) char smc[28672 + 1216];
    int* sA = reinterpret_cast<int*>(smc);               // [112][28]
    int* sW = reinterpret_cast<int*>(smc + 12544);       // [144][28]
    int8_t* sS = reinterpret_cast<int8_t*>(smc);         // overlay after mma: [144][116]
    float* sAf = reinterpret_cast<float*>(smc + 28672);  // 144
    float* sBf = sAf + 144;

    int t = threadIdx.x, w = t >> 5, lane = t & 31;
    int q = lane >> 2, rr = lane & 3;
    int pix0 = blockIdx.x * 112;
    int co0  = blockIdx.y * 144;

    // load A: 672 int4
    {
        const int4* gA = reinterpret_cast<const int4*>(g_qxt + (size_t)pix0 * 96);
#pragma unroll
        for (int it = 0; it < 2; it++) {
            int i = t + it * 448;
            if (i < 672) {
                int r = i / 6, c = i % 6;
                *reinterpret_cast<int4*>(&sA[r * 28 + c * 4]) = gA[i];
            }
        }
    }
    // load W: 864 int4
    {
        const int4* gW = reinterpret_cast<const int4*>(g_qw1 + (size_t)co0 * 96);
#pragma unroll
        for (int it = 0; it < 2; it++) {
            int i = t + it * 448;
            if (i < 864) {
                int r = i / 6, c = i % 6;
                *reinterpret_cast<int4*>(&sW[r * 28 + c * 4]) = gW[i];
            }
        }
    }
    if (t < 144) { sAf[t] = g_A1[co0 + t]; sBf[t] = g_B1[co0 + t]; }
    __syncthreads();

    int acc[9][4];
#pragma unroll
    for (int nb = 0; nb < 9; nb++)
#pragma unroll
        for (int j = 0; j < 4; j++) acc[nb][j] = 0;

    int hb = (w & 1) * 72;
    const int* ap = &sA[((w >> 1) * 16 + q) * 28 + rr];
#pragma unroll
    for (int k = 0; k < 3; k++) {
        int a0 = ap[k * 8];
        int a1 = ap[k * 8 + 8 * 28];
        int a2 = ap[k * 8 + 4];
        int a3 = ap[k * 8 + 8 * 28 + 4];
#pragma unroll
        for (int nb = 0; nb < 9; nb++) {
            const int* bp = &sW[(hb + nb * 8 + q) * 28 + rr + k * 8];
            mma8(acc[nb], a0, a1, a2, a3, bp[0], bp[4]);
        }
    }
    __syncthreads();   // all warps done reading sA/sW before overlay

    // stage quantized bytes [co][pix]
    float inv = g_c[0], cm = g_c[1];
    int pr0 = (w >> 1) * 16 + q, pr1 = pr0 + 8;
#pragma unroll
    for (int nb = 0; nb < 9; nb++) {
        int ca = hb + nb * 8 + rr * 2, cb = ca + 1;
        sS[ca * 116 + pr0] = (int8_t)bnq(acc[nb][0], sAf[ca], sBf[ca], inv, cm);
        sS[cb * 116 + pr0] = (int8_t)bnq(acc[nb][1], sAf[cb], sBf[cb], inv, cm);
        sS[ca * 116 + pr1] = (int8_t)bnq(acc[nb][2], sAf[ca], sBf[ca], inv, cm);
        sS[cb * 116 + pr1] = (int8_t)bnq(acc[nb][3], sAf[cb], sBf[cb], inv, cm);
    }
    __syncthreads();

    // coalesced copy to planar: 144 co x 4 rows x 7 ints = 4032 ints
    int n = pix0 / P_;
    int yy = (pix0 % P_) / W_;
#pragma unroll
    for (int it = 0; it < 9; it++) {
        int i = t + it * 448;
        int co = i / 28, rem = i % 28, seg = rem / 7, wd = rem % 7;
        int val = *reinterpret_cast<const int*>(&sS[co * 116 + seg * 28 + wd * 4]);
        *reinterpret_cast<int*>(
            &g_q1p[(size_t)(co0 + co) * 30720 + n * 960 + (yy + seg + 1) * 32 + wd * 4]) = val;
    }
}

// ---------------- kernel: depthwise 3x3 + bn2 + relu6 + quant ----------------
__global__ __launch_bounds__(288) void k_dw()
{
    __shared__ __align__(16) int s_in[72 * 52];
    __shared__ __align__(16) int s_out[2016];
    int t  = threadIdx.x;
    int b  = blockIdx.x;
    int cg = b & 7;
    int s  = (b >> 3) % 7;
    int n  = b / 56;
    int c0 = cg * 72;

    const int4* g4 = reinterpret_cast<const int4*>(g_q1p);
    int4* s4 = reinterpret_cast<int4*>(s_in);
#pragma unroll
    for (int it = 0; it < 3; it++) {
        int idx = t + it * 288;
        int c = idx / 12, r4 = idx % 12;
        s4[c * 13 + r4] = g4[((c0 + c) * 32 + n) * 60 + s * 8 + r4];
    }
    __syncthreads();

    int c = t % 72, y = t / 72;
    int gc = c0 + c;
    int w0 = g_qw2r[gc * 4 + 0];
    int w1 = g_qw2r[gc * 4 + 1];
    int w2 = g_qw2r[gc * 4 + 2];
    float A = g_A2[gc], Bv = g_B2[gc];
    float inv = g_c[2], cm = g_c[3];

    const int4* sb = s4 + c * 13 + y * 2;
    int4 t0 = sb[0], t1 = sb[1], t2 = sb[2], t3 = sb[3], t4 = sb[4], t5 = sb[5];
    int r0[8] = {t0.x, t0.y, t0.z, t0.w, t1.x, t1.y, t1.z, t1.w};
    int r1[8] = {t2.x, t2.y, t2.z, t2.w, t3.x, t3.y, t3.z, t3.w};
    int r2[8] = {t4.x, t4.y, t4.z, t4.w, t5.x, t5.y, t5.z, t5.w};

    int8_t* so = reinterpret_cast<int8_t*>(s_out);
#pragma unroll
    for (int j = 0; j < 7; j++) {
        int p0 = j ? r0[j - 1] : 0, m0 = r0[j], q0 = r0[j + 1];
        int p1 = j ? r1[j - 1] : 0, m1 = r1[j], q1 = r1[j + 1];
        int p2 = j ? r2[j - 1] : 0, m2 = r2[j], q2 = r2[j + 1];
        int a0 = 0, a1 = 0, a2 = 0, a3 = 0;
        a0 = dpw(p0, m0, 0x5543, w0, a0);
        a1 = dpw(p0, m0, 0x6654, w0, a1);
        a2 = dpw(p0, m0, 0x7765, w0, a2);
        a3 = dpw(m0, q0, 0x4432, w0, a3);
        a0 = dpw(p1, m1, 0x5543, w1, a0);
        a1 = dpw(p1, m1, 0x6654, w1, a1);
        a2 = dpw(p1, m1, 0x7765, w1, a2);
        a3 = dpw(m1, q1, 0x4432, w1, a3);
        a0 = dpw(p2, m2, 0x5543, w2, a0);
        a1 = dpw(p2, m2, 0x6654, w2, a1);
        a2 = dpw(p2, m2, 0x7765, w2, a2);
        a3 = dpw(m2, q2, 0x4432, w2, a3);

        int pixb = (y * 28 + j * 4) * 72 + c;
        so[pixb      ] = (int8_t)bnq(a0, A, Bv, inv, cm);
        so[pixb + 72 ] = (int8_t)bnq(a1, A, Bv, inv, cm);
        so[pixb + 144] = (int8_t)bnq(a2, A, Bv, inv, cm);
        so[pixb + 216] = (int8_t)bnq(a3, A, Bv, inv, cm);
    }
    __syncthreads();

    int pbase = n * P_ + s * 112;
    int* gq2 = reinterpret_cast<int*>(g_q2);
#pragma unroll
    for (int it = 0; it < 7; it++) {
        int idx = t + it * 288;
        int pix = idx / 18, k = idx % 18;
        gq2[(pbase + pix) * 144 + cg * 18 + k] = s_out[idx];
    }
}

// ---------------- kernel: conv3 via mma.sync + cp.async double buffer ----------------
// 112 pix x 48 co, K=576 in 3 chunks of 192; 7 warps each m16 x n48.
// dyn smem ints: A0 @0 (5824), A1 @5824, W0 @11648 (2496), W1 @14144; total 16640 ints.
#define C3A(buf) ((buf) * 5824)
#define C3W(buf) (11648 + (buf) * 2496)
#define C3_SMEM (66560 + 384)

__global__ __launch_bounds__(224) void k_conv3m(const float* __restrict__ x,
                                                float* __restrict__ out)
{
    extern __shared__ __align__(16) int sU[];
    uint32_t sb = smem_u32(sU);
    float* sAf = reinterpret_cast<float*>(sU + 16640);
    float* sBf = sAf + 48;
    float* stg = reinterpret_cast<float*>(sU);   // overlay after final mma

    int t = threadIdx.x, w = t >> 5, lane = t & 31;
    int q = lane >> 2, rr = lane & 3;
    int pix0 = blockIdx.x * 112;
    int co0  = blockIdx.y * 48;

    if (t < 48) { sAf[t] = g_A3[co0 + t]; sBf[t] = g_B3[co0 + t]; }

    // async load of chunk ch into buffer buf
    auto load_chunk = [&](int buf, int ch) {
        uint32_t ab = sb + C3A(buf) * 4;
        uint32_t wb = sb + C3W(buf) * 4;
#pragma unroll
        for (int it = 0; it < 6; it++) {
            int i = t + it * 224;
            int r = i / 12, c = i % 12;
            cpa16(ab + (uint32_t)(r * 52 + c * 4) * 4,
                  g_q2 + (size_t)(pix0 + r) * HID_ + ch * 192 + c * 16);
        }
#pragma unroll
        for (int it = 0; it < 3; it++) {
            int i = t + it * 224;
            if (i < 576) {
                int r = i / 12, c = i % 12;
                cpa16(wb + (uint32_t)(r * 52 + c * 4) * 4,
                      g_qw3 + (size_t)(co0 + r) * HID_ + ch * 192 + c * 16);
            }
        }
    };

    load_chunk(0, 0);
    CPCOMMIT();
    CPWAIT0();
    __syncthreads();

    int acc[6][4];
#pragma unroll
    for (int nb = 0; nb < 6; nb++)
#pragma unroll
        for (int j = 0; j < 4; j++) acc[nb][j] = 0;

#pragma unroll
    for (int ch = 0; ch < 3; ch++) {
        if (ch < 2) { load_chunk((ch + 1) & 1, ch + 1); CPCOMMIT(); }

        const int* sA = sU + C3A(ch & 1);
        const int* sW = sU + C3W(ch & 1);
        const int* ap = &sA[(w * 16 + q) * 52 + rr];
#pragma unroll
        for (int k = 0; k < 6; k++) {
            int a0 = ap[k * 8];
            int a1 = ap[k * 8 + 8 * 52];
            int a2 = ap[k * 8 + 4];
            int a3 = ap[k * 8 + 8 * 52 + 4];
#pragma unroll
            for (int nb = 0; nb < 6; nb++) {
                const int* bp = &sW[(nb * 8 + q) * 52 + rr + k * 8];
                mma8(acc[nb], a0, a1, a2, a3, bp[0], bp[4]);
            }
        }
        if (ch < 2) { CPWAIT0(); __syncthreads(); }
    }
    __syncthreads();   // all warps done with buf0 before stage overlay

    // stage fp32 [co][pix] stride 113
    int pr0 = w * 16 + q, pr1 = pr0 + 8;
#pragma unroll
    for (int nb = 0; nb < 6; nb++) {
        int ca = nb * 8 + rr * 2, cb = ca + 1;
        stg[ca * 113 + pr0] = (float)acc[nb][0];
        stg[cb * 113 + pr0] = (float)acc[nb][1];
        stg[ca * 113 + pr1] = (float)acc[nb][2];
        stg[cb * 113 + pr1] = (float)acc[nb][3];
    }
    __syncthreads();

    int n = pix0 / P_;
    int prow = pix0 % P_;
#pragma unroll
    for (int it = 0; it < 24; it++) {
        int i = t + it * 224;
        int co = i / 112, p = i % 112;
        int off = (n * C_ + co0 + co) * P_ + prow + p;
        out[off] = x[off] + fmaf(stg[co * 113 + p], sAf[co], sBf[co]);
    }
}

// ---------------- launch ----------------
extern "C" void kernel_launch(void* const* d_in, const int* in_sizes, int n_in,
                              void* d_out, int out_size)
{
    const float* x   = (const float*)d_in[0];
    const float* w1  = (const float*)d_in[1];
    const float* w2  = (const float*)d_in[2];
    const float* w3  = (const float*)d_in[3];
    const float* aw1 = (const float*)d_in[4];
    const float* ax1 = (const float*)d_in[5];
    const float* g1  = (const float*)d_in[6];
    const float* b1  = (const float*)d_in[7];
    const float* m1  = (const float*)d_in[8];
    const float* v1  = (const float*)d_in[9];
    const float* aw2 = (const float*)d_in[10];
    const float* ax2 = (const float*)d_in[11];
    const float* g2  = (const float*)d_in[12];
    const float* b2  = (const float*)d_in[13];
    const float* m2  = (const float*)d_in[14];
    const float* v2  = (const float*)d_in[15];
    const float* aw3 = (const float*)d_in[16];
    const float* ax3 = (const float*)d_in[17];
    const float* g3  = (const float*)d_in[18];
    const float* b3  = (const float*)d_in[19];
    const float* m3  = (const float*)d_in[20];
    const float* v3  = (const float*)d_in[21];
    float* out = (float*)d_out;

    cudaFuncSetAttribute(k_conv3m, cudaFuncAttributeMaxDynamicSharedMemorySize, C3_SMEM);

    k_setup<<<32, 256>>>(w1, w2, w3, aw1, ax1, g1, b1, m1, v1,
                         aw2, ax2, g2, b2, m2, v2, aw3, ax3, g3, b3, m3, v3);
    k_zero<<<72, 256>>>();
    k_quantx<<<B_ * 25, 256>>>(x, ax1);
    k_conv1m<<<dim3(NP_ / 112, 4), 448>>>();
    k_dw<<<1792, 288>>>();
    k_conv3m<<<dim3(NP_ / 112, 2), 224, C3_SMEM>>>(x, out);
}